// round 17
// baseline (speedup 1.0000x reference)
#include <cuda_runtime.h>
#include <cuda_bf16.h>
#include <cuda_fp16.h>
#include <cstdint>

#define S_TOT 2048
#define DMODEL 3072
#define NHEADS 48
#define HDIM 64
#define RANK_ 128
#define TLEN 226
#define VLEN 1822

#define K2 (2 * DMODEL)       // 6144: g_ab row stride ([hi|lo])
#define LDB2 (DMODEL + RANK_) // 3200: weight row stride ([W hi | lu hi])
#define MAIN_CH (DMODEL / 64) // 48
#define ALL_CH (MAIN_CH + 2)  // 50

// ---------------- fp32 scratch ----------------------------------------------
__device__ __align__(256) float g_t[S_TOT * 3 * RANK_];

// ---------------- fp16 operand buffers ---------------------------------------
__device__ __align__(256) __half g_ab[(size_t)S_TOT * K2];
__device__ __align__(256) __half g_tb[(size_t)S_TOT * 768];
__device__ __align__(256) __half g_wb[4][(size_t)DMODEL * LDB2];   // q,k,v,o
__device__ __align__(256) __half g_ldb[(size_t)(4 * RANK_) * DMODEL];

// ---------------- attention fp16 planes (head-major) ------------------------
__device__ __align__(256) __half g_qhi[(size_t)NHEADS * S_TOT * HDIM];
__device__ __align__(256) __half g_qlo[(size_t)NHEADS * S_TOT * HDIM];
__device__ __align__(256) __half g_khi[(size_t)NHEADS * S_TOT * HDIM];
__device__ __align__(256) __half g_vthi[(size_t)NHEADS * HDIM * S_TOT];

// ============================================================================
// helpers
// ============================================================================
__device__ __forceinline__ uint32_t s2u(const void* p) {
    return (uint32_t)__cvta_generic_to_shared(p);
}
__device__ __forceinline__ void cpa16(uint32_t s, const void* g) {
    asm volatile("cp.async.cg.shared.global [%0], [%1], 16;" :: "r"(s), "l"(g));
}
__device__ __forceinline__ void cpa_commit() {
    asm volatile("cp.async.commit_group;" ::: "memory");
}
__device__ __forceinline__ void ldsm4(uint32_t* r, uint32_t a) {
    asm volatile("ldmatrix.sync.aligned.m8n8.x4.shared.b16 {%0,%1,%2,%3}, [%4];"
                 : "=r"(r[0]), "=r"(r[1]), "=r"(r[2]), "=r"(r[3]) : "r"(a));
}
__device__ __forceinline__ void ldsm2(uint32_t* r, uint32_t a) {
    asm volatile("ldmatrix.sync.aligned.m8n8.x2.shared.b16 {%0,%1}, [%2];"
                 : "=r"(r[0]), "=r"(r[1]) : "r"(a));
}
__device__ __forceinline__ void mma_f16(float* c, const uint32_t* a, const uint32_t* b) {
    asm volatile(
        "mma.sync.aligned.m16n8k16.row.col.f32.f16.f16.f32 "
        "{%0,%1,%2,%3}, {%4,%5,%6,%7}, {%8,%9}, {%0,%1,%2,%3};"
        : "+f"(c[0]), "+f"(c[1]), "+f"(c[2]), "+f"(c[3])
        : "r"(a[0]), "r"(a[1]), "r"(a[2]), "r"(a[3]), "r"(b[0]), "r"(b[1]));
}
__device__ __forceinline__ void split2h(float x, float y, uint32_t& hi, uint32_t& lo) {
    __half2 h = __floats2half2_rn(x, y);
    float hx = __half2float(__low2half(h)), hy = __half2float(__high2half(h));
    __half2 l = __floats2half2_rn(x - hx, y - hy);
    hi = *reinterpret_cast<uint32_t*>(&h);
    lo = *reinterpret_cast<uint32_t*>(&l);
}
__device__ __forceinline__ uint32_t pack2h(float x, float y) {
    __half2 h = __floats2half2_rn(x, y);
    return *reinterpret_cast<uint32_t*>(&h);
}

// ============================================================================
// split kernels
// ============================================================================
__global__ void splitb1_kernel(const float* __restrict__ src,
                               __half* __restrict__ dst,
                               int K, int dstStride, int dstOff, int n)
{
    int i = blockIdx.x * 256 + threadIdx.x;
    if (i >= n) return;
    int r = i / K, k = i % K;
    dst[(size_t)r * dstStride + dstOff + k] = __float2half_rn(src[i]);
}

__global__ void splitb3_kernel(const float* __restrict__ s0,
                               const float* __restrict__ s1,
                               const float* __restrict__ s2,
                               __half* __restrict__ dst, size_t dstProjStride,
                               int K, int dstStride, int dstOff, int n)
{
    int i = blockIdx.x * 256 + threadIdx.x;
    if (i >= 3 * n) return;
    int p = i / n, j = i % n;
    const float* src = (p == 0) ? s0 : (p == 1) ? s1 : s2;
    int r = j / K, k = j % K;
    dst[p * dstProjStride + (size_t)r * dstStride + dstOff + k] = __float2half_rn(src[j]);
}

__global__ void split_concat_kernel(const float* __restrict__ hid,
                                    const float* __restrict__ enc)
{
    int i = blockIdx.x * 256 + threadIdx.x;
    if (i >= S_TOT * DMODEL) return;
    int r = i / DMODEL, k = i % DMODEL;
    float x = (r < TLEN) ? enc[i] : hid[i - TLEN * DMODEL];
    __half hi = __float2half_rn(x);
    __half lo = __float2half_rn(x - __half2float(hi));
    __half* d = g_ab + (size_t)r * K2;
    d[k] = hi;
    d[DMODEL + k] = lo;
}

__global__ void tsplit_kernel(int nproj)
{
    int n = S_TOT * nproj * RANK_;
    int i = blockIdx.x * 256 + threadIdx.x;
    if (i >= n) return;
    int kw = nproj * RANK_;
    int r = i / kw, k = i % kw;
    int p = k >> 7, kk = k & 127;
    float x = g_t[(size_t)r * kw + k];
    __half hi = __float2half_rn(x);
    __half lo = __float2half_rn(x - __half2float(hi));
    __half* d = g_tb + (size_t)r * 768 + p * 256;
    d[kk] = hi;
    d[128 + kk] = lo;
}

// ============================================================================
// GEMM core: BK=64 physical, B tile resident, A hi(+lo) passes.
// ============================================================================
#define TILE_B 18432
#define STAGE_B (3 * TILE_B)
#define GEMM_SMEM (2 * STAGE_B)   // 110592

struct GemmCore {
    float acc[4][8][4];
    uint32_t smb;
    int lane, wm0, wn0, lrow, lch;

    __device__ __forceinline__ void init(void* sm) {
        smb = s2u(sm);
        int tid = threadIdx.x;
        lane = tid & 31;
        int wid = tid >> 5;
        wm0 = (wid & 1) * 64; wn0 = (wid >> 1) * 64;
        lrow = tid >> 3; lch = tid & 7;
#pragma unroll
        for (int i = 0; i < 4; i++)
#pragma unroll
            for (int j = 0; j < 8; j++)
#pragma unroll
                for (int e = 0; e < 4; e++) acc[i][j][e] = 0.f;
    }

    __device__ __forceinline__ void load_tile(int buf,
                                              const __half* gaHi, const __half* gaLo,
                                              int alda, const __half* gb, int ldb,
                                              int two) {
        uint32_t base = smb + buf * STAGE_B + lrow * 144 + lch * 16;
#pragma unroll
        for (int i = 0; i < 8; i++) {
            int row = lrow + i * 16;
            cpa16(base + i * (16 * 144), gaHi + (size_t)row * alda);
            cpa16(base + TILE_B * 2 + i * (16 * 144), gb + (size_t)row * ldb);
        }
        if (two) {
#pragma unroll
            for (int i = 0; i < 8; i++) {
                int row = lrow + i * 16;
                cpa16(base + TILE_B + i * (16 * 144), gaLo + (size_t)row * alda);
            }
        }
        cpa_commit();
    }

    __device__ __forceinline__ void compute(int buf, int two) {
        uint32_t sawh = smb + buf * STAGE_B
                        + (uint32_t)((wm0 + (lane & 15)) * 144) + ((lane >> 4) << 4);
        uint32_t sbw = smb + buf * STAGE_B + 2 * TILE_B
                       + (uint32_t)((wn0 + (lane & 7)) * 144) + (((lane >> 3) & 1) << 4);
#pragma unroll
        for (int s = 0; s < 4; s++) {
            uint32_t ah[4][4], al[4][4], bf[8][2];
#pragma unroll
            for (int i = 0; i < 4; i++) ldsm4(ah[i], sawh + i * (16 * 144) + s * 32);
            if (two) {
#pragma unroll
                for (int i = 0; i < 4; i++)
                    ldsm4(al[i], sawh + TILE_B + i * (16 * 144) + s * 32);
            }
#pragma unroll
            for (int j = 0; j < 8; j++) ldsm2(bf[j], sbw + j * (8 * 144) + s * 32);
#pragma unroll
            for (int i = 0; i < 4; i++)
#pragma unroll
                for (int j = 0; j < 8; j++)
                    mma_f16(acc[i][j], ah[i], bf[j]);
            if (two) {
#pragma unroll
                for (int i = 0; i < 4; i++)
#pragma unroll
                    for (int j = 0; j < 8; j++)
                        mma_f16(acc[i][j], al[i], bf[j]);
            }
        }
    }

    __device__ __forceinline__ void store(int r0, int c0, const float* bias,
                                          float* C, int ldc, int use_atomic, int permute) {
#pragma unroll
        for (int i = 0; i < 4; i++) {
#pragma unroll
            for (int j = 0; j < 8; j++) {
                int mm = r0 + wm0 + i * 16 + (lane >> 2);
                int nn = c0 + wn0 + j * 8 + (lane & 3) * 2;
                int row0 = mm, row1 = mm + 8;
                if (permute) {
                    row0 = (row0 < TLEN) ? row0 + VLEN : row0 - TLEN;
                    row1 = (row1 < TLEN) ? row1 + VLEN : row1 - TLEN;
                }
                float* p0 = C + (size_t)row0 * ldc + nn;
                float* p1 = C + (size_t)row1 * ldc + nn;
                float b0v = bias ? bias[nn] : 0.f;
                float b1v = bias ? bias[nn + 1] : 0.f;
                if (use_atomic) {
                    atomicAdd(p0,     acc[i][j][0] + b0v);
                    atomicAdd(p0 + 1, acc[i][j][1] + b1v);
                    atomicAdd(p1,     acc[i][j][2] + b0v);
                    atomicAdd(p1 + 1, acc[i][j][3] + b1v);
                } else {
                    p0[0] = acc[i][j][0] + b0v;
                    p0[1] = acc[i][j][1] + b1v;
                    p1[0] = acc[i][j][2] + b0v;
                    p1[1] = acc[i][j][3] + b1v;
                }
            }
        }
    }
};

// generic GEMM; global chunk base = gcb0 + z*chunks, clamped to total_ch.
// bias applied only by the block covering gc==0.
__global__ void __launch_bounds__(128, 2) gemm_hmma(
    const __half* __restrict__ Ah,
    const __half* __restrict__ At, int toff,
    const __half* __restrict__ B, int ldb2,
    const float* __restrict__ bias, float* __restrict__ C, int ldc,
    int gcb0, int chunks, int total_ch, int two_term, int use_atomic, int permute)
{
    extern __shared__ __half sm[];
    GemmCore g;
    g.init(sm);
    const int r0 = blockIdx.y << 7;
    const int c0 = blockIdx.x << 7;
    const int gcb = gcb0 + blockIdx.z * chunks;
    int ch = chunks;
    if (gcb + ch > total_ch) ch = total_ch - gcb;

    auto ldTile = [&](int buf, int gc) {
        const __half *ahi, *alo;
        int alda;
        if (gc < MAIN_CH) {
            ahi = Ah + (size_t)r0 * K2 + gc * 64 + g.lch * 8;
            alo = Ah + (size_t)r0 * K2 + DMODEL + gc * 64 + g.lch * 8;
            alda = K2;
        } else {
            int ct = gc - MAIN_CH;
            ahi = At + (size_t)r0 * 768 + toff + ct * 64 + g.lch * 8;
            alo = At + (size_t)r0 * 768 + toff + 128 + ct * 64 + g.lch * 8;
            alda = 768;
        }
        int bcol = (gc < MAIN_CH) ? gc * 64 : DMODEL + (gc - MAIN_CH) * 64;
        const __half* gb = B + (size_t)c0 * ldb2 + bcol + g.lch * 8;
        g.load_tile(buf, ahi, alo, alda, gb, ldb2, two_term);
    };

    ldTile(0, gcb);
    for (int c = 0; c < ch; c++) {
        if (c + 1 < ch) {
            ldTile((c + 1) & 1, gcb + c + 1);
            asm volatile("cp.async.wait_group 1;" ::: "memory");
        } else {
            asm volatile("cp.async.wait_group 0;" ::: "memory");
        }
        __syncthreads();
        g.compute(c & 1, two_term);
        __syncthreads();
    }
    const float* biasz = (gcb == 0) ? bias : nullptr;
    g.store(r0, c0, biasz, C, ldc, use_atomic, permute);
}

// ============================================================================
// merged q/k/v projection GEMM with fused epilogues
// ============================================================================
__global__ void __launch_bounds__(128, 2) gemm_qkv(
    const __half* __restrict__ Ah, const __half* __restrict__ At,
    const __half* __restrict__ Wbase,
    const float* __restrict__ b0, const float* __restrict__ b1, const float* __restrict__ b2,
    const float* __restrict__ gq, const float* __restrict__ btq,
    const float* __restrict__ gk, const float* __restrict__ btk,
    const float* __restrict__ rc, const float* __restrict__ rs)
{
    extern __shared__ __half sm[];
    GemmCore g;
    g.init(sm);
    const int tid = threadIdx.x;
    const int proj = blockIdx.x / 24;
    const int c0 = (blockIdx.x % 24) << 7;
    const int r0 = blockIdx.y << 7;
    const __half* B = Wbase + (size_t)proj * DMODEL * LDB2;
    const int toff = proj * 256;

    auto ldTile = [&](int buf, int gc) {
        const __half *ahi, *alo;
        int alda;
        if (gc < MAIN_CH) {
            ahi = Ah + (size_t)r0 * K2 + gc * 64 + g.lch * 8;
            alo = Ah + (size_t)r0 * K2 + DMODEL + gc * 64 + g.lch * 8;
            alda = K2;
        } else {
            int ct = gc - MAIN_CH;
            ahi = At + (size_t)r0 * 768 + toff + ct * 64 + g.lch * 8;
            alo = At + (size_t)r0 * 768 + toff + 128 + ct * 64 + g.lch * 8;
            alda = 768;
        }
        int bcol = (gc < MAIN_CH) ? gc * 64 : DMODEL + (gc - MAIN_CH) * 64;
        const __half* gb = B + (size_t)c0 * LDB2 + bcol + g.lch * 8;
        g.load_tile(buf, ahi, alo, alda, gb, LDB2, 1);
    };

    ldTile(0, 0);
    for (int c = 0; c < ALL_CH; c++) {
        if (c + 1 < ALL_CH) {
            ldTile((c + 1) & 1, c + 1);
            asm volatile("cp.async.wait_group 1;" ::: "memory");
        } else {
            asm volatile("cp.async.wait_group 0;" ::: "memory");
        }
        __syncthreads();
        g.compute(c & 1, 1);
        __syncthreads();
    }

    const int lq = g.lane & 3, rq = g.lane >> 2;

    if (proj == 2) {
        __half* st = sm;
#pragma unroll
        for (int i = 0; i < 4; i++) {
#pragma unroll
            for (int j = 0; j < 8; j++) {
                int dl = g.wn0 + j * 8 + lq * 2;
                float bv0 = b2[c0 + dl], bv1 = b2[c0 + dl + 1];
#pragma unroll
                for (int half = 0; half < 2; half++) {
                    int p = g.wm0 + i * 16 + rq + half * 8;
                    st[dl * 136 + p]       = __float2half_rn(g.acc[i][j][2 * half] + bv0);
                    st[(dl + 1) * 136 + p] = __float2half_rn(g.acc[i][j][2 * half + 1] + bv1);
                }
            }
        }
        __syncthreads();
#pragma unroll
        for (int i = 0; i < 16; i++) {
            int d = (tid >> 4) + i * 8;
            int pc = tid & 15;
            uint4 v4 = *reinterpret_cast<uint4*>(st + d * 136 + pc * 8);
            *reinterpret_cast<uint4*>(g_vthi + (size_t)(c0 + d) * S_TOT + r0 + pc * 8) = v4;
        }
        return;
    }

    const float* bias = (proj == 0) ? b0 : b1;
    const float* gamma = (proj == 0) ? gq : gk;
    const float* beta  = (proj == 0) ? btq : btk;
    // Q pre-scaled by (1/8)*log2(e) so attention can use exp2
    const float qscale = (proj == 0) ? 0.180336880f : 1.0f;
    const int head = (c0 + g.wn0) >> 6;

#pragma unroll
    for (int i = 0; i < 4; i++) {
#pragma unroll
        for (int half = 0; half < 2; half++) {
            int pos = r0 + g.wm0 + i * 16 + rq + half * 8;
            float v[16];
            float sum = 0.f, sq = 0.f;
#pragma unroll
            for (int j = 0; j < 8; j++) {
                int d0 = j * 8 + lq * 2;
                float x0 = g.acc[i][j][2 * half]     + bias[c0 + g.wn0 + d0];
                float x1 = g.acc[i][j][2 * half + 1] + bias[c0 + g.wn0 + d0 + 1];
                v[2 * j] = x0; v[2 * j + 1] = x1;
                sum += x0 + x1;
                sq += x0 * x0 + x1 * x1;
            }
            sum += __shfl_xor_sync(0xffffffffu, sum, 1);
            sum += __shfl_xor_sync(0xffffffffu, sum, 2);
            sq  += __shfl_xor_sync(0xffffffffu, sq, 1);
            sq  += __shfl_xor_sync(0xffffffffu, sq, 2);
            float mu = sum * (1.f / 64.f);
            float var = fmaxf(sq * (1.f / 64.f) - mu * mu, 0.f);
            float inv = rsqrtf(var + 1e-5f);

            size_t base = ((size_t)head * S_TOT + pos) * HDIM;
            int rope = (pos >= TLEN);
            int rr = pos - TLEN;
#pragma unroll
            for (int j = 0; j < 8; j++) {
                int d0 = j * 8 + lq * 2;
                float y0 = (v[2 * j]     - mu) * inv * gamma[d0]     + beta[d0];
                float y1 = (v[2 * j + 1] - mu) * inv * gamma[d0 + 1] + beta[d0 + 1];
                if (rope) {
                    float cc0 = rc[rr * HDIM + d0], cc1 = rc[rr * HDIM + d0 + 1];
                    float ss0 = rs[rr * HDIM + d0], ss1 = rs[rr * HDIM + d0 + 1];
                    float t0 = y0 * cc0 - y1 * ss0;
                    float t1 = y1 * cc1 + y0 * ss1;
                    y0 = t0; y1 = t1;
                }
                y0 *= qscale; y1 *= qscale;
                if (proj == 0) {
                    uint32_t hi, lo;
                    split2h(y0, y1, hi, lo);
                    *reinterpret_cast<uint32_t*>(g_qhi + base + d0) = hi;
                    *reinterpret_cast<uint32_t*>(g_qlo + base + d0) = lo;
                } else {
                    *reinterpret_cast<uint32_t*>(g_khi + base + d0) = pack2h(y0, y1);
                }
            }
        }
    }
}

// ============================================================================
// HMMA flash attention: scores fp16 2-term (log2 domain), PV 1-term.
// ============================================================================
#define ASQH 0
#define ASQL 18432
#define ASK  36864
#define ASV  55296
#define ATT_SMEM 73728
#define N_KCH (S_TOT / 64)

__global__ void __launch_bounds__(256, 2) attn_hmma()
{
    extern __shared__ char smc[];
    const int head = blockIdx.y;
    const int q0 = blockIdx.x * 128;
    const int tid = threadIdx.x;
    const int lane = tid & 31;
    const int wid = tid >> 5;
    const uint32_t smb = s2u(smc);

    {
        const __half* Qh = g_qhi + ((size_t)head * S_TOT + q0) * HDIM;
        const __half* Ql = g_qlo + ((size_t)head * S_TOT + q0) * HDIM;
#pragma unroll
        for (int i = 0; i < 4; i++) {
            int idx = tid + i * 256;
            int row = idx >> 3, ch = idx & 7;
            cpa16(smb + ASQH + row * 144 + ch * 16, Qh + row * HDIM + ch * 8);
            cpa16(smb + ASQL + row * 144 + ch * 16, Ql + row * HDIM + ch * 8);
        }
        cpa_commit();
    }

    auto load_kv = [&](int c) {
        int buf = c & 1;
        const __half* Kh = g_khi + ((size_t)head * S_TOT + c * 64) * HDIM;
        uint32_t kb = smb + ASK + buf * 9216;
#pragma unroll
        for (int i = 0; i < 2; i++) {
            int idx = tid + i * 256;
            int row = idx >> 3, ch = idx & 7;
            cpa16(kb + row * 144 + ch * 16, Kh + row * HDIM + ch * 8);
        }
        const __half* Vh = g_vthi + (size_t)head * HDIM * S_TOT + c * 64;
        uint32_t vb = smb + ASV + buf * 9216;
#pragma unroll
        for (int i = 0; i < 2; i++) {
            int idx = tid + i * 256;
            int d = idx >> 3, ch = idx & 7;
            cpa16(vb + d * 144 + ch * 16, Vh + (size_t)d * S_TOT + ch * 8);
        }
        cpa_commit();
    };

    load_kv(0);

    uint32_t aQh[4][4], aQl[4][4];
    float O[8][4];
#pragma unroll
    for (int j = 0; j < 8; j++)
#pragma unroll
        for (int e = 0; e < 4; e++) O[j][e] = 0.f;
    float m0 = -1e30f, m1 = -1e30f, l0 = 0.f, l1 = 0.f;

    for (int c = 0; c < N_KCH; c++) {
        if (c + 1 < N_KCH) {
            load_kv(c + 1);
            asm volatile("cp.async.wait_group 1;" ::: "memory");
        } else {
            asm volatile("cp.async.wait_group 0;" ::: "memory");
        }
        __syncthreads();

        if (c == 0) {
            uint32_t qa = smb + (uint32_t)((wid * 16 + (lane & 15)) * 144)
                          + ((lane >> 4) << 4);
#pragma unroll
            for (int kc = 0; kc < 4; kc++) {
                ldsm4(aQh[kc], qa + ASQH + kc * 32);
                ldsm4(aQl[kc], qa + ASQL + kc * 32);
            }
        }

        int buf = c & 1;
        float s[8][4];
#pragma unroll
        for (int j = 0; j < 8; j++)
#pragma unroll
            for (int e = 0; e < 4; e++) s[j][e] = 0.f;

        uint32_t kb = smb + ASK + buf * 9216 + (uint32_t)((lane & 7) * 144)
                      + (((lane >> 3) & 1) << 4);
#pragma unroll
        for (int kc = 0; kc < 4; kc++) {
#pragma unroll
            for (int j = 0; j < 8; j++) {
                uint32_t bh[2];
                ldsm2(bh, kb + j * (8 * 144) + kc * 32);
                mma_f16(s[j], aQh[kc], bh);
                mma_f16(s[j], aQl[kc], bh);
            }
        }

        float mx0 = -1e30f, mx1 = -1e30f;
#pragma unroll
        for (int j = 0; j < 8; j++) {
            mx0 = fmaxf(mx0, fmaxf(s[j][0], s[j][1]));
            mx1 = fmaxf(mx1, fmaxf(s[j][2], s[j][3]));
        }
        mx0 = fmaxf(mx0, __shfl_xor_sync(0xffffffffu, mx0, 1));
        mx0 = fmaxf(mx0, __shfl_xor_sync(0xffffffffu, mx0, 2));
        mx1 = fmaxf(mx1, __shfl_xor_sync(0xffffffffu, mx1, 1));
        mx1 = fmaxf(mx1, __shfl_xor_sync(0xffffffffu, mx1, 2));
        float mn0 = fmaxf(m0, mx0), mn1 = fmaxf(m1, mx1);
        float cr0 = exp2f(m0 - mn0), cr1 = exp2f(m1 - mn1);
        m0 = mn0; m1 = mn1;

        float rs0 = 0.f, rs1 = 0.f;
#pragma unroll
        for (int j = 0; j < 8; j++) {
            s[j][0] = exp2f(s[j][0] - mn0);
            s[j][1] = exp2f(s[j][1] - mn0);
            s[j][2] = exp2f(s[j][2] - mn1);
            s[j][3] = exp2f(s[j][3] - mn1);
            rs0 += s[j][0] + s[j][1];
            rs1 += s[j][2] + s[j][3];
        }
        rs0 += __shfl_xor_sync(0xffffffffu, rs0, 1);
        rs0 += __shfl_xor_sync(0xffffffffu, rs0, 2);
        rs1 += __shfl_xor_sync(0xffffffffu, rs1, 1);
        rs1 += __shfl_xor_sync(0xffffffffu, rs1, 2);
        l0 = l0 * cr0 + rs0;
        l1 = l1 * cr1 + rs1;

#pragma unroll
        for (int j = 0; j < 8; j++) {
            O[j][0] *= cr0; O[j][1] *= cr0;
            O[j][2] *= cr1; O[j][3] *= cr1;
        }

        uint32_t vb = smb + ASV + buf * 9216 + (uint32_t)((lane & 7) * 144)
                      + (((lane >> 3) & 1) << 4);
#pragma unroll
        for (int ck = 0; ck < 4; ck++) {
            uint32_t ah[4];
            ah[0] = pack2h(s[2 * ck][0],     s[2 * ck][1]);
            ah[1] = pack2h(s[2 * ck][2],     s[2 * ck][3]);
            ah[2] = pack2h(s[2 * ck + 1][0], s[2 * ck + 1][1]);
            ah[3] = pack2h(s[2 * ck + 1][2], s[2 * ck + 1][3]);
#pragma unroll
            for (int jd = 0; jd < 8; jd++) {
                uint32_t bh[2];
                ldsm2(bh, vb + jd * (8 * 144) + ck * 32);
                mma_f16(O[jd], ah, bh);
            }
        }
        __syncthreads();
    }

    float i0 = 1.f / l0, i1 = 1.f / l1;
    int r = q0 + wid * 16 + (lane >> 2);
    int cb = head * HDIM + (lane & 3) * 2;
    __half* row0 = g_ab + (size_t)r * K2;
    __half* row1 = g_ab + (size_t)(r + 8) * K2;
#pragma unroll
    for (int jd = 0; jd < 8; jd++) {
        int col = cb + jd * 8;
        uint32_t hi, lo;
        split2h(O[jd][0] * i0, O[jd][1] * i0, hi, lo);
        *reinterpret_cast<uint32_t*>(row0 + col) = hi;
        *reinterpret_cast<uint32_t*>(row0 + DMODEL + col) = lo;
        split2h(O[jd][2] * i1, O[jd][3] * i1, hi, lo);
        *reinterpret_cast<uint32_t*>(row1 + col) = hi;
        *reinterpret_cast<uint32_t*>(row1 + DMODEL + col) = lo;
    }
}

// ============================================================================
extern "C" void kernel_launch(void* const* d_in, const int* in_sizes, int n_in,
                              void* d_out, int out_size)
{
    const float* hid = (const float*)d_in[0];
    const float* enc = (const float*)d_in[1];
    const float* rc  = (const float*)d_in[2];
    const float* rs  = (const float*)d_in[3];
    const float* Wq  = (const float*)d_in[4];  const float* bq = (const float*)d_in[5];
    const float* Wk  = (const float*)d_in[6];  const float* bk = (const float*)d_in[7];
    const float* Wv  = (const float*)d_in[8];  const float* bv = (const float*)d_in[9];
    const float* Wo  = (const float*)d_in[10]; const float* bo = (const float*)d_in[11];
    const float* lqd = (const float*)d_in[12]; const float* lqu = (const float*)d_in[13];
    const float* lkd = (const float*)d_in[14]; const float* lku = (const float*)d_in[15];
    const float* lvd = (const float*)d_in[16]; const float* lvu = (const float*)d_in[17];
    const float* lpd = (const float*)d_in[18]; const float* lpu = (const float*)d_in[19];
    const float* gq  = (const float*)d_in[20]; const float* btq = (const float*)d_in[21];
    const float* gk  = (const float*)d_in[22]; const float* btk = (const float*)d_in[23];

    static cudaStream_t s2 = nullptr;
    static cudaEvent_t evFork = nullptr, evSplits = nullptr, evS2done = nullptr;
    static cudaEvent_t evAttn = nullptr, evLora = nullptr;
    static int attr_done = 0;
    if (!attr_done) {
        cudaFuncSetAttribute(attn_hmma, cudaFuncAttributeMaxDynamicSharedMemorySize,
                             ATT_SMEM);
        cudaFuncSetAttribute(gemm_hmma, cudaFuncAttributeMaxDynamicSharedMemorySize,
                             GEMM_SMEM);
        cudaFuncSetAttribute(gemm_qkv, cudaFuncAttributeMaxDynamicSharedMemorySize,
                             GEMM_SMEM);
        cudaStreamCreateWithFlags(&s2, cudaStreamNonBlocking);
        cudaEventCreateWithFlags(&evFork, cudaEventDisableTiming);
        cudaEventCreateWithFlags(&evSplits, cudaEventDisableTiming);
        cudaEventCreateWithFlags(&evS2done, cudaEventDisableTiming);
        cudaEventCreateWithFlags(&evAttn, cudaEventDisableTiming);
        cudaEventCreateWithFlags(&evLora, cudaEventDisableTiming);
        attr_done = 1;
    }

    float* pt;
    __half *pab, *ptb, *pldb, *pwbase;
    cudaGetSymbolAddress((void**)&pt, g_t);
    cudaGetSymbolAddress((void**)&pab, g_ab);
    cudaGetSymbolAddress((void**)&ptb, g_tb);
    cudaGetSymbolAddress((void**)&pldb, g_ldb);
    cudaGetSymbolAddress((void**)&pwbase, g_wb);
    __half* pwo  = pwbase + (size_t)3 * DMODEL * LDB2;
    __half* plpd = pldb + (size_t)(3 * RANK_) * DMODEL;

    const int nHD = S_TOT * DMODEL;
    const int nW  = DMODEL * DMODEL;
    const int nLD = RANK_ * DMODEL;
    const int nLU = DMODEL * RANK_;

    dim3 qkv_grid(72, S_TOT / 128, 1);
    dim3 oproj_grid1(DMODEL / 128, S_TOT / 128, 2);  // chunks 0..33 (no lora tail)
    dim3 oproj_grid2(DMODEL / 128, S_TOT / 128, 1);  // chunks 34..49 (has tail)
    dim3 lora3_grid(3, S_TOT / 128, 8);
    dim3 lora1_grid(1, S_TOT / 128, 8);
    const int LORA_CH = MAIN_CH / 8;                 // 6

    // ================= fork: weight prep on s2 =================
    cudaEventRecord(evFork, 0);
    cudaStreamWaitEvent(s2, evFork, 0);
    splitb3_kernel<<<(3 * nW + 255) / 256, 256, 0, s2>>>(Wq, Wk, Wv, pwbase,
                                                         (size_t)DMODEL * LDB2,
                                                         DMODEL, LDB2, 0, nW);
    splitb3_kernel<<<(3 * nLU + 255) / 256, 256, 0, s2>>>(lqu, lku, lvu, pwbase,
                                                          (size_t)DMODEL * LDB2,
                                                          RANK_, LDB2, DMODEL, nLU);
    splitb3_kernel<<<(3 * nLD + 255) / 256, 256, 0, s2>>>(lqd, lkd, lvd, pldb,
                                                          (size_t)RANK_ * DMODEL,
                                                          DMODEL, DMODEL, 0, nLD);
    cudaEventRecord(evSplits, s2);
    splitb1_kernel<<<(nW + 255) / 256, 256, 0, s2>>>(Wo, pwo, DMODEL, LDB2, 0, nW);
    splitb1_kernel<<<(nLU + 255) / 256, 256, 0, s2>>>(lpu, pwo, RANK_, LDB2, DMODEL, nLU);
    splitb1_kernel<<<(nLD + 255) / 256, 256, 0, s2>>>(lpd, plpd, DMODEL, DMODEL, 0, nLD);
    cudaMemsetAsync(d_out, 0, (size_t)out_size * sizeof(float), s2);
    cudaEventRecord(evS2done, s2);

    // ================= main chain =================
    split_concat_kernel<<<(nHD + 255) / 256, 256>>>(hid, enc);
    cudaMemsetAsync(pt, 0, S_TOT * 3 * RANK_ * sizeof(float));
    cudaStreamWaitEvent(0, evSplits, 0);
    gemm_hmma<<<lora3_grid, 128, GEMM_SMEM>>>(pab, nullptr, 0, pldb, DMODEL,
                                              nullptr, pt, 3 * RANK_,
                                              0, LORA_CH, MAIN_CH, 0, 1, 0);
    tsplit_kernel<<<(S_TOT * 3 * RANK_ + 255) / 256, 256>>>(3);
    gemm_qkv<<<qkv_grid, 128, GEMM_SMEM>>>(pab, ptb, pwbase, bq, bk, bv,
                                           gq, btq, gk, btk, rc, rs);
    cudaMemsetAsync(pt, 0, S_TOT * RANK_ * sizeof(float));

    attn_hmma<<<dim3(S_TOT / 128, NHEADS), 256, ATT_SMEM>>>();
    cudaEventRecord(evAttn, 0);

    // o-proj lora chain on s2, concurrent with oproj part 1
    cudaStreamWaitEvent(s2, evAttn, 0);
    gemm_hmma<<<lora1_grid, 128, GEMM_SMEM, s2>>>(pab, nullptr, 0, plpd, DMODEL,
                                                  nullptr, pt, RANK_,
                                                  0, LORA_CH, MAIN_CH, 0, 1, 0);
    tsplit_kernel<<<(S_TOT * RANK_ + 255) / 256, 256, 0, s2>>>(1);
    cudaEventRecord(evLora, s2);

    // oproj part 1 (chunks 0..33, no tail dependency)
    cudaStreamWaitEvent(0, evS2done, 0);
    gemm_hmma<<<oproj_grid1, 128, GEMM_SMEM>>>(pab, ptb, 0, pwo, LDB2,
                                               bo, (float*)d_out, DMODEL,
                                               0, 17, ALL_CH, 1, 1, 1);
    // oproj part 2 (chunks 34..49, includes lora tail)
    cudaStreamWaitEvent(0, evLora, 0);
    gemm_hmma<<<oproj_grid2, 128, GEMM_SMEM>>>(pab, ptb, 0, pwo, LDB2,
                                               bo, (float*)d_out, DMODEL,
                                               34, 16, ALL_CH, 1, 1, 1);
}